// round 15
// baseline (speedup 1.0000x reference)
#include <cuda_runtime.h>
#include <cstdint>

// Scatter-add message passing: out[dst] += x[src]
// x: [N, 64] fp32; edge_index: [2, E] int32.
//
// R15 = R14 body (kernel at LTS floor, 41.4-41.8us across 4 runs) + PDL:
// the zero pass (~1.3us, write-only on out) overlaps the scatter's read-only
// prologue (index loads + gathers). cudaGridDependencySynchronize() sits
// between the gather phase and the RED phase, so REDs stay ordered after the
// zero-store flush. Zeroing per replay is mandatory (REDs accumulate across
// graph replays otherwise).

__global__ void k_zero(float4* __restrict__ out, int n4) {
    int i = blockIdx.x * blockDim.x + threadIdx.x;
    if (i < n4) out[i] = make_float4(0.f, 0.f, 0.f, 0.f);
    // Signal dependents may launch; stores are flushed by kernel completion,
    // which cudaGridDependencySynchronize() in the dependent waits for.
    cudaTriggerProgrammaticLaunchCompletion();
}

__device__ __forceinline__ void red_v4(float* out, int dst, int c, float4 v) {
    float4* op = (float4*)(out + (size_t)dst * 64) + c;
    asm volatile("red.global.add.v4.f32 [%0], {%1, %2, %3, %4};"
                 :: "l"(op), "f"(v.x), "f"(v.y), "f"(v.z), "f"(v.w)
                 : "memory");
}

__global__ void __launch_bounds__(256, 8)
mp_scatter4_kernel(const float* __restrict__ x,
                   const int* __restrict__ ei,
                   float* __restrict__ out,
                   int E, int G) {
    int tid = blockIdx.x * blockDim.x + threadIdx.x;
    int g = tid >> 4;           // group of 4 consecutive edges
    int c = tid & 15;           // float4 chunk within the 64-float row

    if (g < G) {
        int e0 = g << 2;
        int n = min(4, E - e0);     // edges in this group (tail-safe)

        int dst[4], src[4];
        if (n == 4) {               // aligned: e0 % 4 == 0
            int4 d4 = __ldg((const int4*)(ei + e0));
            int4 s4 = __ldg((const int4*)(ei + E + e0));
            dst[0] = d4.x; dst[1] = d4.y; dst[2] = d4.z; dst[3] = d4.w;
            src[0] = s4.x; src[1] = s4.y; src[2] = s4.z; src[3] = s4.w;
        } else {
            #pragma unroll
            for (int k = 0; k < 4; k++) {
                int e = e0 + ((k < n) ? k : 0);
                dst[k] = __ldg(ei + e);
                src[k] = __ldg(ei + E + e);
            }
        }

        // Read-only prologue: all 4 gathers in flight. Runs concurrently
        // with the tail of k_zero (PDL), since out is untouched here.
        float4 v[4];
        #pragma unroll
        for (int k = 0; k < 4; k++)
            v[k] = __ldg((const float4*)(x + (size_t)src[k] * 64) + c);

        // Wait for k_zero's stores to be visible before any RED.
        cudaGridDependencySynchronize();

        #pragma unroll
        for (int k = 0; k < 4; k++)
            if (k < n) red_v4(out, dst[k], c, v[k]);
    } else {
        cudaGridDependencySynchronize();
    }
}

extern "C" void kernel_launch(void* const* d_in, const int* in_sizes, int n_in,
                              void* d_out, int out_size) {
    const float* x = (const float*)d_in[0];
    const int* ei = (const int*)d_in[1];
    float* out = (float*)d_out;

    int E = in_sizes[1] / 2;            // edge_index is [2, E]
    int G = (E + 3) / 4;                // groups of 4 edges

    int n4 = out_size / 4;              // float4 count of out
    int tb = 256;
    k_zero<<<(n4 + tb - 1) / tb, tb>>>((float4*)out, n4);

    long long total = (long long)G * 16;
    int blocks = (int)((total + tb - 1) / tb);

    // Launch scatter with programmatic dependency on k_zero: it may begin
    // its read-only prologue before k_zero fully completes.
    cudaLaunchConfig_t cfg = {};
    cfg.gridDim = dim3((unsigned)blocks);
    cfg.blockDim = dim3((unsigned)tb);
    cfg.dynamicSmemBytes = 0;
    cfg.stream = 0;
    cudaLaunchAttribute attr[1];
    attr[0].id = cudaLaunchAttributeProgrammaticStreamSerialization;
    attr[0].val.programmaticStreamSerializationAllowed = 1;
    cfg.attrs = attr;
    cfg.numAttrs = 1;
    cudaLaunchKernelEx(&cfg, mp_scatter4_kernel, x, ei, out, E, G);
}